// round 2
// baseline (speedup 1.0000x reference)
#include <cuda_runtime.h>
#include <cstdint>

#define MM 4096
#define NN 4096
#define KK 4096
#define BM 128
#define BN 256
#define BK 32
#define NKT (KK / BK)            // 128 k-iterations
#define XS_STRIDE 36             // BK + 4 pad -> conflict-free A fragment LDS
#define XS_SIZE (BM * XS_STRIDE) // 4608 floats
#define WS_SIZE (BK * BN)        // 8192 floats (fragment-permuted)
#define SMEM_BYTES ((2 * XS_SIZE + 2 * WS_SIZE) * 4) // 102400 B

__device__ __forceinline__ uint32_t f2tf(float f) {
    uint32_t r;
    asm("cvt.rna.tf32.f32 %0, %1;" : "=r"(r) : "f"(f));
    return r;
}

// Store x tile (128 x 32) into smem, rounded to tf32. 4 float4 per thread.
__device__ __forceinline__ void store_x_tile(float* xsb, const float4* xr, int tid) {
#pragma unroll
    for (int f = 0; f < 4; f++) {
        int slot = tid + f * 256;
        int m = slot >> 3, k4 = slot & 7;
        float4 v = xr[f];
        float4 o;
        o.x = __uint_as_float(f2tf(v.x));
        o.y = __uint_as_float(f2tf(v.y));
        o.z = __uint_as_float(f2tf(v.z));
        o.w = __uint_as_float(f2tf(v.w));
        *(float4*)&xsb[m * XS_STRIDE + k4 * 4] = o;
    }
}

// Dequant + store W tile (32 x 256) into fragment-permuted smem layout.
// Thread owns column c = tid; packed int i covers k-chunk r=i (k local r*8+kk).
// Permuted layout: ws[r*2048 + c*8 + 2*(kk%4) + kk/4]
//   => consumer lane reads float2 at tile_base + lane*2 = exact b0/b1 fragment.
__device__ __forceinline__ void store_w_tile(float* wsb, const int* wr4, float s, float z, int tid) {
#pragma unroll
    for (int i = 0; i < 4; i++) {
        int p = wr4[i];
        float v[8];
#pragma unroll
        for (int kk = 0; kk < 8; kk++)
            v[kk] = ((float)((p >> (4 * kk)) & 15) - z) * s;
        float4 lo, hi;
        lo.x = __uint_as_float(f2tf(v[0]));
        lo.y = __uint_as_float(f2tf(v[4]));
        lo.z = __uint_as_float(f2tf(v[1]));
        lo.w = __uint_as_float(f2tf(v[5]));
        hi.x = __uint_as_float(f2tf(v[2]));
        hi.y = __uint_as_float(f2tf(v[6]));
        hi.z = __uint_as_float(f2tf(v[3]));
        hi.w = __uint_as_float(f2tf(v[7]));
        float* base = wsb + i * (BN * 8) + tid * 8;
        *(float4*)base = lo;
        *(float4*)(base + 4) = hi;
    }
}

__global__ void __launch_bounds__(256, 1)
gemm_w4(const float* __restrict__ x, const int* __restrict__ wq,
        const float* __restrict__ scales, const float* __restrict__ zeros,
        const float* __restrict__ bias, float* __restrict__ out)
{
    extern __shared__ float smem[];
    float* xs = smem;                 // 2 x XS_SIZE
    float* ws = smem + 2 * XS_SIZE;   // 2 x WS_SIZE

    const int tid = threadIdx.x;
    const int lane = tid & 31;
    const int warp = tid >> 5;
    const int wm = warp >> 2;  // 0..1  (M)
    const int wn = warp & 3;   // 0..3  (N)
    const int bm0 = blockIdx.y * BM;
    const int bn0 = blockIdx.x * BN;

    float acc[4][8][4];
#pragma unroll
    for (int mf = 0; mf < 4; mf++)
#pragma unroll
        for (int nf = 0; nf < 8; nf++)
#pragma unroll
            for (int r = 0; r < 4; r++) acc[mf][nf][r] = 0.0f;

    float4 xr[4];
    int wr4[4];
    float sv, zv;

    // ---- prologue: fetch + stage tile kt=0 into buffer 0 ----
    {
#pragma unroll
        for (int f = 0; f < 4; f++) {
            int slot = tid + f * 256;
            int m = slot >> 3, k4 = slot & 7;
            xr[f] = *(const float4*)&x[(bm0 + m) * KK + k4 * 4];
        }
        sv = scales[bn0 + tid];
        zv = zeros[bn0 + tid];
#pragma unroll
        for (int i = 0; i < 4; i++)
            wr4[i] = wq[i * NN + bn0 + tid];
        store_x_tile(xs, xr, tid);
        store_w_tile(ws, wr4, sv, zv, tid);
        __syncthreads();
    }

    const int arow_base = (wm * 64 + (lane >> 2)) * XS_STRIDE + (lane & 3);
    const int bcol_base = (wn * 8) * 64 + lane * 2;

#pragma unroll 1
    for (int kt = 0; kt < NKT; ++kt) {
        const int cur = kt & 1;

        // prefetch next tile into registers (overlaps with compute below)
        if (kt + 1 < NKT) {
            const int kn = kt + 1;
#pragma unroll
            for (int f = 0; f < 4; f++) {
                int slot = tid + f * 256;
                int m = slot >> 3, k4 = slot & 7;
                xr[f] = *(const float4*)&x[(bm0 + m) * KK + kn * BK + k4 * 4];
            }
            const int g = kn >> 2;  // group = (kn*32)/128
            sv = scales[g * NN + bn0 + tid];
            zv = zeros[g * NN + bn0 + tid];
#pragma unroll
            for (int i = 0; i < 4; i++)
                wr4[i] = wq[(kn * 4 + i) * NN + bn0 + tid];
        }

        const float* xb = xs + cur * XS_SIZE;
        const float* wb = ws + cur * WS_SIZE;

#pragma unroll
        for (int ks = 0; ks < 4; ks++) {
            uint32_t a[4][4];
#pragma unroll
            for (int mf = 0; mf < 4; mf++) {
                const float* ap = xb + arow_base + mf * 16 * XS_STRIDE + ks * 8;
                a[mf][0] = __float_as_uint(ap[0]);
                a[mf][1] = __float_as_uint(ap[8 * XS_STRIDE]);
                a[mf][2] = __float_as_uint(ap[4]);
                a[mf][3] = __float_as_uint(ap[8 * XS_STRIDE + 4]);
            }
            uint32_t b[8][2];
#pragma unroll
            for (int nf = 0; nf < 8; nf++) {
                const float2 t = *(const float2*)(wb + ks * (BN * 8) + bcol_base + nf * 64);
                b[nf][0] = __float_as_uint(t.x);
                b[nf][1] = __float_as_uint(t.y);
            }
#pragma unroll
            for (int mf = 0; mf < 4; mf++)
#pragma unroll
                for (int nf = 0; nf < 8; nf++)
                    asm("mma.sync.aligned.m16n8k8.row.col.f32.tf32.tf32.f32 "
                        "{%0,%1,%2,%3}, {%4,%5,%6,%7}, {%8,%9}, {%0,%1,%2,%3};"
                        : "+f"(acc[mf][nf][0]), "+f"(acc[mf][nf][1]),
                          "+f"(acc[mf][nf][2]), "+f"(acc[mf][nf][3])
                        : "r"(a[mf][0]), "r"(a[mf][1]), "r"(a[mf][2]), "r"(a[mf][3]),
                          "r"(b[nf][0]), "r"(b[nf][1]));
        }

        // stage next tile into the other buffer
        if (kt + 1 < NKT) {
            float* xbn = xs + (cur ^ 1) * XS_SIZE;
            float* wbn = ws + (cur ^ 1) * WS_SIZE;
            store_x_tile(xbn, xr, tid);
            store_w_tile(wbn, wr4, sv, zv, tid);
            __syncthreads();
        }
    }

    // ---- epilogue: add bias, write out ----
#pragma unroll
    for (int mf = 0; mf < 4; mf++) {
        const int rm = bm0 + wm * 64 + mf * 16 + (lane >> 2);
#pragma unroll
        for (int nf = 0; nf < 8; nf++) {
            const int cn = bn0 + wn * 64 + nf * 8 + 2 * (lane & 3);
            const float2 bv = *(const float2*)&bias[cn];
            float2 o0 = make_float2(acc[mf][nf][0] + bv.x, acc[mf][nf][1] + bv.y);
            float2 o1 = make_float2(acc[mf][nf][2] + bv.x, acc[mf][nf][3] + bv.y);
            *(float2*)&out[rm * NN + cn] = o0;
            *(float2*)&out[(rm + 8) * NN + cn] = o1;
        }
    }
}

extern "C" void kernel_launch(void* const* d_in, const int* in_sizes, int n_in,
                              void* d_out, int out_size) {
    const float* x      = (const float*)d_in[0];
    const int*   wq     = (const int*)d_in[1];
    const float* scales = (const float*)d_in[2];
    const float* zeros  = (const float*)d_in[3];
    const float* bias   = (const float*)d_in[4];
    float* out = (float*)d_out;

    cudaFuncSetAttribute(gemm_w4, cudaFuncAttributeMaxDynamicSharedMemorySize, SMEM_BYTES);
    dim3 grid(NN / BN, MM / BM);  // 16 x 32 = 512 CTAs
    gemm_w4<<<grid, 256, SMEM_BYTES>>>(x, wq, scales, zeros, bias, out);
}

// round 5
// speedup vs baseline: 1.0907x; 1.0907x over previous
#include <cuda_runtime.h>
#include <cstdint>

#define MM 4096
#define NN 4096
#define KK 4096
#define BM 128
#define BN 256
#define BK 32
#define NKT (KK / BK)            // 128 k-iterations
#define XS_STRIDE 36             // BK + 4 pad -> conflict-free A fragment LDS
#define XS_SIZE (BM * XS_STRIDE) // 4608 floats
#define WS_SIZE (BK * BN)        // 8192 floats (fragment-permuted)
#define SMEM_BYTES ((2 * XS_SIZE + 2 * WS_SIZE) * 4) // 102400 B

__device__ __forceinline__ uint32_t f2tf(float f) {
    uint32_t r;
    asm("cvt.rna.tf32.f32 %0, %1;" : "=r"(r) : "f"(f));
    return r;
}

// nibble kk of packed word -> float bits of exact (16 + nib), one shift + one LOP3
template <int KKI>
__device__ __forceinline__ float nib16(uint32_t p) {
    uint32_t t = (KKI < 5) ? (p << (19 - 4 * KKI)) : (p >> (4 * KKI - 19));
    return __uint_as_float((t & 0x00780000u) | 0x41800000u);
}

// A staging: thread covers row=tid>>2, cols (tid&3)*8 .. +7 (two float4), tf32-rounded
__device__ __forceinline__ void store_x_tile(float* xsb, const float4* xr, int rowA, int cbA) {
    float* dst = xsb + rowA * XS_STRIDE + cbA;
#pragma unroll
    for (int f = 0; f < 2; f++) {
        float4 v = xr[f];
        float4 o;
        o.x = __uint_as_float(f2tf(v.x));
        o.y = __uint_as_float(f2tf(v.y));
        o.z = __uint_as_float(f2tf(v.z));
        o.w = __uint_as_float(f2tf(v.w));
        *(float4*)(dst + f * 4) = o;
    }
}

// B staging: thread owns column nB, two packed words (i0, i0+1).
// Permuted layout: ws[i*2048 + n*8 + 2*(kk%4) + kk/4] -> consumer float2 at lane*2
__device__ __forceinline__ void store_w_tile(float* wsb, const int* wr2, int i0, int nB,
                                             float sv, float c2) {
#pragma unroll
    for (int i = 0; i < 2; i++) {
        const uint32_t p = (uint32_t)wr2[i];
        float4 lo, hi;
        lo.x = __uint_as_float(f2tf(fmaf(nib16<0>(p), sv, c2)));
        lo.y = __uint_as_float(f2tf(fmaf(nib16<4>(p), sv, c2)));
        lo.z = __uint_as_float(f2tf(fmaf(nib16<1>(p), sv, c2)));
        lo.w = __uint_as_float(f2tf(fmaf(nib16<5>(p), sv, c2)));
        hi.x = __uint_as_float(f2tf(fmaf(nib16<2>(p), sv, c2)));
        hi.y = __uint_as_float(f2tf(fmaf(nib16<6>(p), sv, c2)));
        hi.z = __uint_as_float(f2tf(fmaf(nib16<3>(p), sv, c2)));
        hi.w = __uint_as_float(f2tf(fmaf(nib16<7>(p), sv, c2)));
        float* base = wsb + (i0 + i) * (BN * 8) + nB * 8;
        *(float4*)base = lo;
        *(float4*)(base + 4) = hi;
    }
}

__global__ void __launch_bounds__(512, 1)
gemm_w4(const float* __restrict__ x, const int* __restrict__ wq,
        const float* __restrict__ scales, const float* __restrict__ zeros,
        const float* __restrict__ bias, float* __restrict__ out)
{
    extern __shared__ float smem[];
    float* xs = smem;                 // 2 x XS_SIZE
    float* ws = smem + 2 * XS_SIZE;   // 2 x WS_SIZE

    const int tid = threadIdx.x;
    const int lane = tid & 31;
    const int warp = tid >> 5;
    const int wm = warp >> 2;  // 0..3  (M, 32-rows each)
    const int wn = warp & 3;   // 0..3  (N, 64-cols each)
    const int bm0 = blockIdx.y * BM;
    const int bn0 = blockIdx.x * BN;

    // producer mapping
    const int rowA = tid >> 2;
    const int cbA = (tid & 3) * 8;
    const int nB = tid & 255;
    const int i0 = (tid >> 8) * 2;   // words i0, i0+1
    const float* xrow = x + (size_t)(bm0 + rowA) * KK + cbA;
    const int gn = bn0 + nB;

    float acc[2][8][4];
#pragma unroll
    for (int mf = 0; mf < 2; mf++)
#pragma unroll
        for (int nf = 0; nf < 8; nf++)
#pragma unroll
            for (int r = 0; r < 4; r++) acc[mf][nf][r] = 0.0f;

    float4 ab[2][2];
    int bb[2][2];
    float sv2[2], c22[2];

    // ---- prologue: fetch + stage tile kt=0 into buffer 0 ----
    {
#pragma unroll
        for (int f = 0; f < 2; f++) ab[0][f] = *(const float4*)(xrow + f * 4);
#pragma unroll
        for (int i = 0; i < 2; i++) bb[0][i] = wq[(size_t)(i0 + i) * NN + gn];
        float s = scales[gn], z = zeros[gn];
        sv2[0] = s;
        c22[0] = -(z + 16.0f) * s;
        store_x_tile(xs, ab[0], rowA, cbA);
        store_w_tile(ws, bb[0], i0, nB, sv2[0], c22[0]);
        __syncthreads();
    }

    const int arow_base = (wm * 32 + (lane >> 2)) * XS_STRIDE + (lane & 3);
    const int bcol_base = wn * 512 + lane * 2;

#pragma unroll 1
    for (int kt = 0; kt < NKT; ++kt) {
        const int cur = kt & 1;

        // prefetch next tile into registers (overlaps with compute below)
        if (kt + 1 < NKT) {
            const int kn = kt + 1;
#pragma unroll
            for (int f = 0; f < 2; f++)
                ab[cur ^ 1][f] = *(const float4*)(xrow + (size_t)kn * BK + f * 4);
#pragma unroll
            for (int i = 0; i < 2; i++)
                bb[cur ^ 1][i] = wq[(size_t)(kn * 4 + i0 + i) * NN + gn];
            const int g = kn >> 2;
            float s = scales[(size_t)g * NN + gn];
            float z = zeros[(size_t)g * NN + gn];
            sv2[cur ^ 1] = s;
            c22[cur ^ 1] = -(z + 16.0f) * s;
        }

        const float* xb = xs + cur * XS_SIZE;
        const float* wb = ws + cur * WS_SIZE;

#pragma unroll
        for (int ks = 0; ks < 4; ks++) {
            uint32_t a[2][4];
#pragma unroll
            for (int mf = 0; mf < 2; mf++) {
                const float* ap = xb + arow_base + mf * 16 * XS_STRIDE + ks * 8;
                a[mf][0] = __float_as_uint(ap[0]);
                a[mf][1] = __float_as_uint(ap[8 * XS_STRIDE]);
                a[mf][2] = __float_as_uint(ap[4]);
                a[mf][3] = __float_as_uint(ap[8 * XS_STRIDE + 4]);
            }
#pragma unroll
            for (int nf = 0; nf < 8; nf++) {
                const float2 t = *(const float2*)(wb + ks * (BN * 8) + bcol_base + nf * 64);
                const uint32_t b0 = __float_as_uint(t.x);
                const uint32_t b1 = __float_as_uint(t.y);
#pragma unroll
                for (int mf = 0; mf < 2; mf++)
                    asm("mma.sync.aligned.m16n8k8.row.col.f32.tf32.tf32.f32 "
                        "{%0,%1,%2,%3}, {%4,%5,%6,%7}, {%8,%9}, {%0,%1,%2,%3};"
                        : "+f"(acc[mf][nf][0]), "+f"(acc[mf][nf][1]),
                          "+f"(acc[mf][nf][2]), "+f"(acc[mf][nf][3])
                        : "r"(a[mf][0]), "r"(a[mf][1]), "r"(a[mf][2]), "r"(a[mf][3]),
                          "r"(b0), "r"(b1));
            }
        }

        // stage next tile into the other buffer
        if (kt + 1 < NKT) {
            store_x_tile(xs + (cur ^ 1) * XS_SIZE, ab[cur ^ 1], rowA, cbA);
            store_w_tile(ws + (cur ^ 1) * WS_SIZE, bb[cur ^ 1], i0, nB,
                         sv2[cur ^ 1], c22[cur ^ 1]);
            __syncthreads();
        }
    }

    // ---- epilogue: add bias, write out ----
#pragma unroll
    for (int mf = 0; mf < 2; mf++) {
        const int rm = bm0 + wm * 32 + mf * 16 + (lane >> 2);
#pragma unroll
        for (int nf = 0; nf < 8; nf++) {
            const int cn = bn0 + wn * 64 + nf * 8 + 2 * (lane & 3);
            const float2 bv = *(const float2*)&bias[cn];
            float2 o0 = make_float2(acc[mf][nf][0] + bv.x, acc[mf][nf][1] + bv.y);
            float2 o1 = make_float2(acc[mf][nf][2] + bv.x, acc[mf][nf][3] + bv.y);
            *(float2*)&out[(size_t)rm * NN + cn] = o0;
            *(float2*)&out[(size_t)(rm + 8) * NN + cn] = o1;
        }
    }
}

extern "C" void kernel_launch(void* const* d_in, const int* in_sizes, int n_in,
                              void* d_out, int out_size) {
    const float* x      = (const float*)d_in[0];
    const int*   wq     = (const int*)d_in[1];
    const float* scales = (const float*)d_in[2];
    const float* zeros  = (const float*)d_in[3];
    const float* bias   = (const float*)d_in[4];
    float* out = (float*)d_out;

    cudaFuncSetAttribute(gemm_w4, cudaFuncAttributeMaxDynamicSharedMemorySize, SMEM_BYTES);
    dim3 grid(NN / BN, MM / BM);  // 16 x 32 = 512 CTAs
    gemm_w4<<<grid, 512, SMEM_BYTES>>>(x, wq, scales, zeros, bias, out);
}

// round 8
// speedup vs baseline: 1.4965x; 1.3720x over previous
#include <cuda_runtime.h>
#include <cstdint>

#define MM 4096
#define NN 4096
#define KK 4096
#define BM 128
#define BN 256
#define BK 32
#define NKT (KK / BK)             // 128 k-iterations
#define AS_BYTES 8192             // 128 rows x 64B fp16 (swizzled)
#define BS_BYTES 16384            // 2 k16-blocks x 256 cols x 32B
#define SMEM_BYTES (2 * AS_BYTES + 2 * BS_BYTES)  // 49152

static __device__ __forceinline__ uint32_t s2u(const void* p) {
    uint32_t a;
    asm("{ .reg .u64 t; cvta.to.shared.u64 t, %1; cvt.u32.u64 %0, t; }" : "=r"(a) : "l"(p));
    return a;
}

// pack two f32 -> f16x2 {lo, hi}, round-nearest
static __device__ __forceinline__ uint32_t pack_h2(float lo, float hi) {
    uint32_t r;
    asm("cvt.rn.f16x2.f32 %0, %1, %2;" : "=r"(r) : "f"(hi), "f"(lo));
    return r;
}

// nibble kk of packed word -> float bits of exact (16 + nib): shift + lop3
template <int KKI>
static __device__ __forceinline__ float nib16(uint32_t p) {
    uint32_t t = (KKI < 5) ? (p << (19 - 4 * KKI)) : (p >> (4 * KKI - 19));
    return __uint_as_float((t & 0x00780000u) | 0x41800000u);
}

static __device__ __forceinline__ void sts128(uint32_t a, uint32_t r0, uint32_t r1,
                                              uint32_t r2, uint32_t r3) {
    asm volatile("st.shared.v4.b32 [%0], {%1,%2,%3,%4};"
                 :: "r"(a), "r"(r0), "r"(r1), "r"(r2), "r"(r3) : "memory");
}

static __device__ __forceinline__ void lds64(uint32_t a, uint32_t& r0, uint32_t& r1) {
    asm volatile("ld.shared.v2.b32 {%0,%1}, [%2];" : "=r"(r0), "=r"(r1) : "r"(a));
}

static __device__ __forceinline__ void ldmx4(uint32_t a, uint32_t* r) {
    asm volatile("ldmatrix.sync.aligned.m8n8.x4.shared.b16 {%0,%1,%2,%3}, [%4];"
                 : "=r"(r[0]), "=r"(r[1]), "=r"(r[2]), "=r"(r[3]) : "r"(a));
}

__global__ void __launch_bounds__(512, 1)
gemm_w4(const float* __restrict__ x, const int* __restrict__ wq,
        const float* __restrict__ scales, const float* __restrict__ zeros,
        const float* __restrict__ bias, float* __restrict__ out)
{
    extern __shared__ char smem[];
    const uint32_t sb = s2u(smem);
    const uint32_t xs = sb;                     // 2 x AS_BYTES
    const uint32_t ws = sb + 2 * AS_BYTES;      // 2 x BS_BYTES

    const int tid = threadIdx.x;
    const int lane = tid & 31;
    const int warp = tid >> 5;
    const int wm = warp >> 2;  // 0..3 (M, 32 rows)
    const int wn = warp & 3;   // 0..3 (N, 64 cols)
    const int bm0 = blockIdx.y * BM;
    const int bn0 = blockIdx.x * BN;

    // ---------------- producer mapping ----------------
    const int rowA = tid >> 2;
    const int segA = tid & 3;
    const uint32_t a_sts_off = (uint32_t)rowA * 64 + (uint32_t)((segA ^ ((rowA >> 1) & 3)) << 4);
    const float* xrow = x + (size_t)(bm0 + rowA) * KK + segA * 8;

    const int nB = tid & 255;
    const int blk = tid >> 8;           // k16 block 0/1
    const int i0 = blk * 2;             // packed words i0, i0+1
    const int gB = nB >> 2, qB = nB & 3, pgB = gB & 1;
    const uint32_t b_sts0_off = (uint32_t)(blk * 8192 + gB * 128 + ((qB + 4 * pgB) << 4));
    const uint32_t b_sts1_off = (uint32_t)(blk * 8192 + gB * 128 + ((qB + 4 * (1 ^ pgB)) << 4));
    const int gn = bn0 + nB;

    // ---------------- consumer mapping ----------------
    // A (ldmatrix x4): row = wm*32 + mf*16 + (lane&15), half = lane>>4
    const int ahalf = lane >> 4;
    const int rsw = ((lane & 15) >> 1) & 3;
    const uint32_t a_ld_base = (uint32_t)(wm * 2048 + (lane & 15) * 64);
    // B: per-lane constant within a col-group record
    const int cB = lane & 3;
    const uint32_t Lb = (uint32_t)((lane >> 4) * 128 + (((lane >> 2) & 3) << 4)
                                 + ((((cB >> 1)) ^ (lane >> 4)) << 6) + ((cB & 1) << 3));
    const uint32_t b_ld_base = (uint32_t)(wn * 2048) + Lb;

    float acc[2][8][4];
#pragma unroll
    for (int mf = 0; mf < 2; mf++)
#pragma unroll
        for (int nf = 0; nf < 8; nf++)
#pragma unroll
            for (int r = 0; r < 4; r++) acc[mf][nf][r] = 0.0f;

    float4 ab[2][2];
    int bb[2][2];
    float sv2[2], c22[2];

    // stage tile kt into smem buffer buf from register set cb
    auto stage = [&](int buf, int cb) {
        // A: 8 floats -> 4 f16x2 -> one STS.128
        const float4 v0 = ab[cb][0], v1 = ab[cb][1];
        sts128(xs + (uint32_t)buf * AS_BYTES + a_sts_off,
               pack_h2(v0.x, v0.y), pack_h2(v0.z, v0.w),
               pack_h2(v1.x, v1.y), pack_h2(v1.z, v1.w));
        // B: dequant 16 nibbles (2 words) in fp32, pack pairs, 2x STS.128
        const float sv = sv2[cb], c2 = c22[cb];
        const uint32_t pe = (uint32_t)bb[cb][0];  // even word: pairs j=0..3
        const uint32_t po = (uint32_t)bb[cb][1];  // odd word:  pairs j=4..7
        uint32_t e0 = pack_h2(fmaf(nib16<0>(pe), sv, c2), fmaf(nib16<1>(pe), sv, c2));
        uint32_t e1 = pack_h2(fmaf(nib16<2>(pe), sv, c2), fmaf(nib16<3>(pe), sv, c2));
        uint32_t e2 = pack_h2(fmaf(nib16<4>(pe), sv, c2), fmaf(nib16<5>(pe), sv, c2));
        uint32_t e3 = pack_h2(fmaf(nib16<6>(pe), sv, c2), fmaf(nib16<7>(pe), sv, c2));
        uint32_t o0 = pack_h2(fmaf(nib16<0>(po), sv, c2), fmaf(nib16<1>(po), sv, c2));
        uint32_t o1 = pack_h2(fmaf(nib16<2>(po), sv, c2), fmaf(nib16<3>(po), sv, c2));
        uint32_t o2 = pack_h2(fmaf(nib16<4>(po), sv, c2), fmaf(nib16<5>(po), sv, c2));
        uint32_t o3 = pack_h2(fmaf(nib16<6>(po), sv, c2), fmaf(nib16<7>(po), sv, c2));
        const uint32_t wb = ws + (uint32_t)buf * BS_BYTES;
        sts128(wb + b_sts0_off, e0, o0, e1, o1);   // chunks 0,1
        sts128(wb + b_sts1_off, e2, o2, e3, o3);   // chunks 2,3
    };

    // ---- prologue ----
    {
#pragma unroll
        for (int f = 0; f < 2; f++) ab[0][f] = *(const float4*)(xrow + f * 4);
#pragma unroll
        for (int i = 0; i < 2; i++) bb[0][i] = wq[(size_t)(i0 + i) * NN + gn];
        float s = scales[gn], z = zeros[gn];
        sv2[0] = s;
        c22[0] = -(z + 16.0f) * s;
        stage(0, 0);
        __syncthreads();
    }

#pragma unroll 1
    for (int kt = 0; kt < NKT; ++kt) {
        const int cur = kt & 1;

        // prefetch next tile into registers
        if (kt + 1 < NKT) {
            const int kn = kt + 1;
#pragma unroll
            for (int f = 0; f < 2; f++)
                ab[cur ^ 1][f] = *(const float4*)(xrow + (size_t)kn * BK + f * 4);
#pragma unroll
            for (int i = 0; i < 2; i++)
                bb[cur ^ 1][i] = wq[(size_t)(kn * 4 + i0 + i) * NN + gn];
            const int g = kn >> 2;
            float s = scales[(size_t)g * NN + gn];
            float z = zeros[(size_t)g * NN + gn];
            sv2[cur ^ 1] = s;
            c22[cur ^ 1] = -(z + 16.0f) * s;
        }

        const uint32_t xb = xs + (uint32_t)cur * AS_BYTES;
        const uint32_t wbuf = ws + (uint32_t)cur * BS_BYTES;

#pragma unroll
        for (int ks = 0; ks < 2; ks++) {
            uint32_t a[2][4];
#pragma unroll
            for (int mf = 0; mf < 2; mf++)
                ldmx4(xb + a_ld_base + (uint32_t)(mf * 1024)
                         + (uint32_t)((((ks << 1) | ahalf) ^ rsw) << 4), a[mf]);
#pragma unroll
            for (int nf = 0; nf < 8; nf++) {
                uint32_t b0, b1;
                lds64(wbuf + (uint32_t)(ks * 8192) + b_ld_base + (uint32_t)(nf * 256), b0, b1);
#pragma unroll
                for (int mf = 0; mf < 2; mf++)
                    asm("mma.sync.aligned.m16n8k16.row.col.f32.f16.f16.f32 "
                        "{%0,%1,%2,%3}, {%4,%5,%6,%7}, {%8,%9}, {%0,%1,%2,%3};"
                        : "+f"(acc[mf][nf][0]), "+f"(acc[mf][nf][1]),
                          "+f"(acc[mf][nf][2]), "+f"(acc[mf][nf][3])
                        : "r"(a[mf][0]), "r"(a[mf][1]), "r"(a[mf][2]), "r"(a[mf][3]),
                          "r"(b0), "r"(b1));
            }
        }

        // stage next tile into the other buffer
        if (kt + 1 < NKT) {
            __syncthreads();            // all consumers done with buffer cur^1
            stage(cur ^ 1, cur ^ 1);
            __syncthreads();
        }
    }

    // ---- epilogue: add bias, write out ----
#pragma unroll
    for (int mf = 0; mf < 2; mf++) {
        const int rm = bm0 + wm * 32 + mf * 16 + (lane >> 2);
#pragma unroll
        for (int nf = 0; nf < 8; nf++) {
            const int cn = bn0 + wn * 64 + nf * 8 + 2 * (lane & 3);
            const float2 bv = *(const float2*)&bias[cn];
            float2 o0 = make_float2(acc[mf][nf][0] + bv.x, acc[mf][nf][1] + bv.y);
            float2 o1 = make_float2(acc[mf][nf][2] + bv.x, acc[mf][nf][3] + bv.y);
            *(float2*)&out[(size_t)rm * NN + cn] = o0;
            *(float2*)&out[(size_t)(rm + 8) * NN + cn] = o1;
        }
    }
}

extern "C" void kernel_launch(void* const* d_in, const int* in_sizes, int n_in,
                              void* d_out, int out_size) {
    const float* x      = (const float*)d_in[0];
    const int*   wq     = (const int*)d_in[1];
    const float* scales = (const float*)d_in[2];
    const float* zeros  = (const float*)d_in[3];
    const float* bias   = (const float*)d_in[4];
    float* out = (float*)d_out;

    cudaFuncSetAttribute(gemm_w4, cudaFuncAttributeMaxDynamicSharedMemorySize, SMEM_BYTES);
    dim3 grid(NN / BN, MM / BM);  // 16 x 32 = 512 CTAs
    gemm_w4<<<grid, 512, SMEM_BYTES>>>(x, wq, scales, zeros, bias, out);
}

// round 13
// speedup vs baseline: 2.2972x; 1.5351x over previous
#include <cuda_runtime.h>
#include <cstdint>

#define MM 4096
#define NN 4096
#define KK 4096
#define BM 128
#define BN 128
#define BK 32
#define NKT (KK / BK)             // 128 k-iterations
#define AS_BYTES 8192             // 128 rows x 64B fp16 (swizzled)
#define BS_BYTES 8192             // 2 k16-blocks x 128 cols x 32B
#define SMEM_BYTES (2 * AS_BYTES + 2 * BS_BYTES)  // 32768

static __device__ __forceinline__ uint32_t s2u(const void* p) {
    uint32_t a;
    asm("{ .reg .u64 t; cvta.to.shared.u64 t, %1; cvt.u32.u64 %0, t; }" : "=r"(a) : "l"(p));
    return a;
}

// pack two f32 -> f16x2 {lo, hi}, round-nearest
static __device__ __forceinline__ uint32_t pack_h2(float lo, float hi) {
    uint32_t r;
    asm("cvt.rn.f16x2.f32 %0, %1, %2;" : "=r"(r) : "f"(hi), "f"(lo));
    return r;
}

// nibble kk of packed word -> float bits of exact (16 + nib): shift + lop3
template <int KKI>
static __device__ __forceinline__ float nib16(uint32_t p) {
    uint32_t t = (KKI < 5) ? (p << (19 - 4 * KKI)) : (p >> (4 * KKI - 19));
    return __uint_as_float((t & 0x00780000u) | 0x41800000u);
}

static __device__ __forceinline__ void sts128(uint32_t a, uint32_t r0, uint32_t r1,
                                              uint32_t r2, uint32_t r3) {
    asm volatile("st.shared.v4.b32 [%0], {%1,%2,%3,%4};"
                 :: "r"(a), "r"(r0), "r"(r1), "r"(r2), "r"(r3) : "memory");
}

static __device__ __forceinline__ void lds64(uint32_t a, uint32_t& r0, uint32_t& r1) {
    asm volatile("ld.shared.v2.b32 {%0,%1}, [%2];" : "=r"(r0), "=r"(r1) : "r"(a));
}

static __device__ __forceinline__ void ldmx4(uint32_t a, uint32_t* r) {
    asm volatile("ldmatrix.sync.aligned.m8n8.x4.shared.b16 {%0,%1,%2,%3}, [%4];"
                 : "=r"(r[0]), "=r"(r[1]), "=r"(r[2]), "=r"(r[3]) : "r"(a));
}

__global__ void __launch_bounds__(256, 2)
gemm_w4(const float* __restrict__ x, const int* __restrict__ wq,
        const float* __restrict__ scales, const float* __restrict__ zeros,
        const float* __restrict__ bias, float* __restrict__ out)
{
    extern __shared__ char smem[];
    const uint32_t sb = s2u(smem);
    const uint32_t xs = sb;                     // 2 x AS_BYTES
    const uint32_t ws = sb + 2 * AS_BYTES;      // 2 x BS_BYTES

    const int tid = threadIdx.x;
    const int lane = tid & 31;
    const int warp = tid >> 5;
    const int wm = warp >> 2;  // 0..1 (M, 64 rows)
    const int wn = warp & 3;   // 0..3 (N, 32 cols)
    const int bm0 = blockIdx.y * BM;
    const int bn0 = blockIdx.x * BN;

    // ---------------- producer mapping ----------------
    // A: thread covers row rowA = tid>>1, 16 cols at halfA*16
    const int rowA = tid >> 1;
    const int halfA = tid & 1;
    const uint32_t asw = (uint32_t)((rowA >> 1) & 3);
    const uint32_t a_sts0 = (uint32_t)rowA * 64 + ((((uint32_t)halfA * 2 + 0) ^ asw) << 4);
    const uint32_t a_sts1 = (uint32_t)rowA * 64 + ((((uint32_t)halfA * 2 + 1) ^ asw) << 4);
    const float* xrow = x + (size_t)(bm0 + rowA) * KK + halfA * 16;

    // B: thread owns column nB, k16 block blk, packed words {i0, i0+1}
    const int nB = tid & 127;
    const int blk = tid >> 7;
    const int i0 = blk * 2;
    const int gB = nB >> 2, qB = nB & 3, pgB = gB & 1;
    const uint32_t b_sts0 = (uint32_t)(blk * 4096 + gB * 128 + ((qB + 4 * pgB) << 4));
    const uint32_t b_sts1 = (uint32_t)(blk * 4096 + gB * 128 + ((qB + 4 * (1 ^ pgB)) << 4));
    const int gn = bn0 + nB;

    // ---------------- consumer mapping ----------------
    const int ahalf = lane >> 4;
    const int rsw = ((lane & 15) >> 1) & 3;
    const uint32_t a_ld_base = (uint32_t)(wm * 4096 + (lane & 15) * 64);
    const int cB = lane & 3;
    const uint32_t Lb = (uint32_t)((lane >> 4) * 128 + (((lane >> 2) & 3) << 4)
                                 + (((cB >> 1) ^ (lane >> 4)) << 6) + ((cB & 1) << 3));
    const uint32_t b_ld_base = (uint32_t)(wn * 1024) + Lb;

    float acc[4][4][4];
#pragma unroll
    for (int mf = 0; mf < 4; mf++)
#pragma unroll
        for (int nf = 0; nf < 4; nf++)
#pragma unroll
            for (int r = 0; r < 4; r++) acc[mf][nf][r] = 0.0f;

    float4 ar[4];
    int br[2];
    float sv, c2;

    auto stage = [&](int buf) {
        // A: 16 floats -> 8 f16x2 -> 2x STS.128
        const uint32_t xb = xs + (uint32_t)buf * AS_BYTES;
        sts128(xb + a_sts0,
               pack_h2(ar[0].x, ar[0].y), pack_h2(ar[0].z, ar[0].w),
               pack_h2(ar[1].x, ar[1].y), pack_h2(ar[1].z, ar[1].w));
        sts128(xb + a_sts1,
               pack_h2(ar[2].x, ar[2].y), pack_h2(ar[2].z, ar[2].w),
               pack_h2(ar[3].x, ar[3].y), pack_h2(ar[3].z, ar[3].w));
        // B: dequant 16 nibbles in fp32, pack pairs, 2x STS.128
        const uint32_t pe = (uint32_t)br[0];
        const uint32_t po = (uint32_t)br[1];
        uint32_t e0 = pack_h2(fmaf(nib16<0>(pe), sv, c2), fmaf(nib16<1>(pe), sv, c2));
        uint32_t e1 = pack_h2(fmaf(nib16<2>(pe), sv, c2), fmaf(nib16<3>(pe), sv, c2));
        uint32_t e2 = pack_h2(fmaf(nib16<4>(pe), sv, c2), fmaf(nib16<5>(pe), sv, c2));
        uint32_t e3 = pack_h2(fmaf(nib16<6>(pe), sv, c2), fmaf(nib16<7>(pe), sv, c2));
        uint32_t o0 = pack_h2(fmaf(nib16<0>(po), sv, c2), fmaf(nib16<1>(po), sv, c2));
        uint32_t o1 = pack_h2(fmaf(nib16<2>(po), sv, c2), fmaf(nib16<3>(po), sv, c2));
        uint32_t o2 = pack_h2(fmaf(nib16<4>(po), sv, c2), fmaf(nib16<5>(po), sv, c2));
        uint32_t o3 = pack_h2(fmaf(nib16<6>(po), sv, c2), fmaf(nib16<7>(po), sv, c2));
        const uint32_t wb = ws + (uint32_t)buf * BS_BYTES;
        sts128(wb + b_sts0, e0, o0, e1, o1);
        sts128(wb + b_sts1, e2, o2, e3, o3);
    };

    // ---- prologue: fetch + stage tile 0 into buffer 0 ----
    {
#pragma unroll
        for (int f = 0; f < 4; f++) ar[f] = *(const float4*)(xrow + f * 4);
#pragma unroll
        for (int i = 0; i < 2; i++) br[i] = wq[(size_t)(i0 + i) * NN + gn];
        float s = scales[gn], z = zeros[gn];
        sv = s;
        c2 = -(z + 16.0f) * s;
        stage(0);
        __syncthreads();
    }

#pragma unroll 1
    for (int kt = 0; kt < NKT; ++kt) {
        const int cur = kt & 1;

        // prefetch tile kt+1 into registers (consumed by stage() below)
        if (kt + 1 < NKT) {
            const int kn = kt + 1;
#pragma unroll
            for (int f = 0; f < 4; f++)
                ar[f] = *(const float4*)(xrow + (size_t)kn * BK + f * 4);
#pragma unroll
            for (int i = 0; i < 2; i++)
                br[i] = wq[(size_t)(kn * 4 + i0 + i) * NN + gn];
            const int g = kn >> 2;
            float s = scales[(size_t)g * NN + gn];
            float z = zeros[(size_t)g * NN + gn];
            sv = s;
            c2 = -(z + 16.0f) * s;
        }

        const uint32_t xb = xs + (uint32_t)cur * AS_BYTES;
        const uint32_t wbuf = ws + (uint32_t)cur * BS_BYTES;

#pragma unroll
        for (int ks = 0; ks < 2; ks++) {
            uint32_t a[4][4];
#pragma unroll
            for (int mf = 0; mf < 4; mf++)
                ldmx4(xb + a_ld_base + (uint32_t)(mf * 1024)
                         + (uint32_t)((((ks << 1) | ahalf) ^ rsw) << 4), a[mf]);
#pragma unroll
            for (int nf = 0; nf < 4; nf++) {
                uint32_t b0, b1;
                lds64(wbuf + (uint32_t)(ks * 4096) + b_ld_base + (uint32_t)(nf * 256), b0, b1);
#pragma unroll
                for (int mf = 0; mf < 4; mf++)
                    asm("mma.sync.aligned.m16n8k16.row.col.f32.f16.f16.f32 "
                        "{%0,%1,%2,%3}, {%4,%5,%6,%7}, {%8,%9}, {%0,%1,%2,%3};"
                        : "+f"(acc[mf][nf][0]), "+f"(acc[mf][nf][1]),
                          "+f"(acc[mf][nf][2]), "+f"(acc[mf][nf][3])
                        : "r"(a[mf][0]), "r"(a[mf][1]), "r"(a[mf][2]), "r"(a[mf][3]),
                          "r"(b0), "r"(b1));
            }
        }

        // stage tile kt+1 into the other buffer; single barrier per tile
        if (kt + 1 < NKT) {
            stage(cur ^ 1);
            __syncthreads();
        }
    }

    // ---- epilogue: add bias, write out ----
#pragma unroll
    for (int mf = 0; mf < 4; mf++) {
        const int rm = bm0 + wm * 64 + mf * 16 + (lane >> 2);
#pragma unroll
        for (int nf = 0; nf < 4; nf++) {
            const int cn = bn0 + wn * 32 + nf * 8 + 2 * (lane & 3);
            const float2 bv = *(const float2*)&bias[cn];
            float2 o0 = make_float2(acc[mf][nf][0] + bv.x, acc[mf][nf][1] + bv.y);
            float2 o1 = make_float2(acc[mf][nf][2] + bv.x, acc[mf][nf][3] + bv.y);
            *(float2*)&out[(size_t)rm * NN + cn] = o0;
            *(float2*)&out[(size_t)(rm + 8) * NN + cn] = o1;
        }
    }
}

extern "C" void kernel_launch(void* const* d_in, const int* in_sizes, int n_in,
                              void* d_out, int out_size) {
    const float* x      = (const float*)d_in[0];
    const int*   wq     = (const int*)d_in[1];
    const float* scales = (const float*)d_in[2];
    const float* zeros  = (const float*)d_in[3];
    const float* bias   = (const float*)d_in[4];
    float* out = (float*)d_out;

    cudaFuncSetAttribute(gemm_w4, cudaFuncAttributeMaxDynamicSharedMemorySize, SMEM_BYTES);
    dim3 grid(NN / BN, MM / BM);  // 32 x 32 = 1024 CTAs
    gemm_w4<<<grid, 256, SMEM_BYTES>>>(x, wq, scales, zeros, bias, out);
}